// round 15
// baseline (speedup 1.0000x reference)
#include <cuda_runtime.h>
#include <cuda_fp16.h>
#include <mma.h>
#include <math.h>

#define NNODES 4096
#define MAXDEG 256
#define ALPHA  0.2f
#define NN64   ((size_t)NNODES * 64)
#define SPLITK 4

// ---------------- scratch (no allocations allowed) ----------------
__device__ int    g_cnt[NNODES];
__device__ int    g_idx[NNODES * MAXDEG];
__device__ __half g_h1h[8 * NNODES * 64];   // layer1 features, fp16 gather table
__device__ float  g_s1a[8 * NNODES];
__device__ float  g_s2a[8 * NNODES];
__device__ float  g_x2 [NNODES * 512];      // elu(hp) fp32 (GEMM2 input)
__device__ float  g_h2p[SPLITK * NNODES * 64]; // layer2 split-K partials
__device__ __half g_h2h[NNODES * 64];       // layer2 features, fp16 gather table
__device__ float  g_s1b[NNODES];
__device__ float  g_s2b[NNODES];
__device__ int    g_tilecnt[32];            // split-K fixup counters (self-reset)

__device__ __forceinline__ float lrelu(float x) { return x > 0.f ? x : ALPHA * x; }
__device__ __forceinline__ void grid_dep_wait() {
    asm volatile("griddepcontrol.wait;" ::: "memory");
}

// ------ fp16 2-way-split GEMM core: 128x64 tile, 8 warps (4m x 2n of 32x32) ----
// x = hi + lo (both fp16); a*b = ah*bh + ah*bl + al*bh (al*bl ~2^-22, dropped).
struct SmemGemm {
    union {
        struct {
            __half AsH[128][40];
            __half AsL[128][40];
            __half BsH[32][72];
            __half BsL[32][72];
        };
        float Cs[128][68];
    };
};

using AFragH = nvcuda::wmma::fragment<nvcuda::wmma::matrix_a, 16, 16, 16,
                                      __half, nvcuda::wmma::row_major>;
using BFragH = nvcuda::wmma::fragment<nvcuda::wmma::matrix_b, 16, 16, 16,
                                      __half, nvcuda::wmma::row_major>;
using CFragH = nvcuda::wmma::fragment<nvcuda::wmma::accumulator, 16, 16, 16, float>;

__device__ __forceinline__ void split_h(float x, __half* hi, __half* lo) {
    __half h = __float2half_rn(x);
    *hi = h;
    *lo = __float2half_rn(x - __half2float(h));
}

template <int KLEN>
__device__ __forceinline__ void gemm_core(SmemGemm& sm, const float* __restrict__ A,
                                          int lda, const float* __restrict__ Bb,
                                          int m0, int kb0, CFragH c[2][2]) {
    using namespace nvcuda::wmma;
    int tid = threadIdx.x;
    int warp = tid >> 5;
    int wm = warp & 3, wn = warp >> 2;
    int ar = tid >> 1, ac = (tid & 1) * 16;     // A: 128 rows x 32 cols, 16 f/thread
    int br = tid >> 3, bc = (tid & 7) * 8;      // B: 32 rows x 64 cols, 8 f/thread

    for (int kb = kb0; kb < kb0 + KLEN; kb += 32) {
        const float* Ag = A + (size_t)(m0 + ar) * lda + kb + ac;
        float av[16];
        *(float4*)&av[0]  = *(const float4*)(Ag + 0);
        *(float4*)&av[4]  = *(const float4*)(Ag + 4);
        *(float4*)&av[8]  = *(const float4*)(Ag + 8);
        *(float4*)&av[12] = *(const float4*)(Ag + 12);
        const float* Bg = Bb + (size_t)(kb + br) * 64 + bc;
        float bv[8];
        *(float4*)&bv[0] = *(const float4*)(Bg + 0);
        *(float4*)&bv[4] = *(const float4*)(Bg + 4);

        #pragma unroll
        for (int e = 0; e < 16; e++)
            split_h(av[e], &sm.AsH[ar][ac + e], &sm.AsL[ar][ac + e]);
        #pragma unroll
        for (int e = 0; e < 8; e++)
            split_h(bv[e], &sm.BsH[br][bc + e], &sm.BsL[br][bc + e]);
        __syncthreads();

        #pragma unroll
        for (int k = 0; k < 32; k += 16) {
            AFragH ah[2], al[2];
            BFragH bh[2], bl[2];
            #pragma unroll
            for (int f = 0; f < 2; f++) {
                load_matrix_sync(ah[f], &sm.AsH[wm * 32 + f * 16][k], 40);
                load_matrix_sync(al[f], &sm.AsL[wm * 32 + f * 16][k], 40);
                load_matrix_sync(bh[f], &sm.BsH[k][wn * 32 + f * 16], 72);
                load_matrix_sync(bl[f], &sm.BsL[k][wn * 32 + f * 16], 72);
            }
            #pragma unroll
            for (int fm = 0; fm < 2; fm++)
                #pragma unroll
                for (int fn = 0; fn < 2; fn++) {
                    mma_sync(c[fm][fn], al[fm], bh[fn], c[fm][fn]);
                    mma_sync(c[fm][fn], ah[fm], bl[fn], c[fm][fn]);
                    mma_sync(c[fm][fn], ah[fm], bh[fn], c[fm][fn]);
                }
        }
        __syncthreads();
    }
}

// ------- layer1: K=256, grid (32,1,8); fused scores + fp16 table epilogue ------
__global__ __launch_bounds__(256)
void gemm1_tc(const float* __restrict__ A, const float* __restrict__ B,
              __half* __restrict__ Ch, const float* __restrict__ avec,
              float* __restrict__ s1, float* __restrict__ s2) {
    using namespace nvcuda::wmma;
    __shared__ SmemGemm sm;
    int m0 = blockIdx.x * 128;
    int hd = blockIdx.z;
    int warp = threadIdx.x >> 5;
    int wm = warp & 3, wn = warp >> 2;

    CFragH c[2][2];
    #pragma unroll
    for (int fm = 0; fm < 2; fm++)
        #pragma unroll
        for (int fn = 0; fn < 2; fn++) fill_fragment(c[fm][fn], 0.f);

    gemm_core<256>(sm, A, 256, B + (size_t)hd * 256 * 64, m0, 0, c);

    #pragma unroll
    for (int fm = 0; fm < 2; fm++)
        #pragma unroll
        for (int fn = 0; fn < 2; fn++)
            store_matrix_sync(&sm.Cs[wm * 32 + fm * 16][wn * 32 + fn * 16],
                              c[fm][fn], 68, mem_row_major);
    __syncthreads();

    // fp16 gather table: 128 rows x 32 half2
    __half2* Hb = (__half2*)(Ch + (size_t)hd * NN64);
    for (int idx = threadIdx.x; idx < 128 * 32; idx += 256) {
        int r = idx >> 5, d2 = idx & 31;
        Hb[(size_t)(m0 + r) * 32 + d2] =
            __floats2half2_rn(sm.Cs[r][d2 * 2], sm.Cs[r][d2 * 2 + 1]);
    }
    // fused scores: thread per row
    if (threadIdx.x < 128) {
        int r = threadIdx.x;
        const float* a1 = avec + hd * 128;
        float p1 = 0.f, p2 = 0.f;
        #pragma unroll
        for (int d = 0; d < 64; d++) {
            float v = sm.Cs[r][d];
            p1 += v * a1[d];
            p2 += v * a1[64 + d];
        }
        s1[(size_t)hd * NNODES + m0 + r] = p1;
        s2[(size_t)hd * NNODES + m0 + r] = p2;
    }
}

// ------- layer1 attention + fused CSR build: block=row, warp=head --------------
__global__ __launch_bounds__(256)
void att1_csr(const float* __restrict__ adj, const __half2* __restrict__ hh,
              const float* __restrict__ s1, const float* __restrict__ s2,
              int* __restrict__ cnt, int* __restrict__ idx,
              float* __restrict__ out) {
    int row  = blockIdx.x;
    int tid  = threadIdx.x;       // 256
    int head = tid >> 5;
    int lane = tid & 31;

    __shared__ int   s_nbr[MAXDEG];
    __shared__ int   s_cnt;
    __shared__ float s_w[8][MAXDEG];

    // CSR scan of this row (independent of gemm1; overlaps it via PDL)
    if (tid == 0) s_cnt = 0;
    __syncthreads();
    const float4* r = (const float4*)(adj + (size_t)row * NNODES);
    for (int c = tid; c < NNODES / 4; c += 256) {
        float4 v = r[c];
        if (v.x > 0.f) { int p = atomicAdd(&s_cnt, 1); if (p < MAXDEG) s_nbr[p] = c * 4 + 0; }
        if (v.y > 0.f) { int p = atomicAdd(&s_cnt, 1); if (p < MAXDEG) s_nbr[p] = c * 4 + 1; }
        if (v.z > 0.f) { int p = atomicAdd(&s_cnt, 1); if (p < MAXDEG) s_nbr[p] = c * 4 + 2; }
        if (v.w > 0.f) { int p = atomicAdd(&s_cnt, 1); if (p < MAXDEG) s_nbr[p] = c * 4 + 3; }
    }
    __syncthreads();
    int n = min(s_cnt, MAXDEG);
    if (tid == 0) cnt[row] = n;
    for (int i = tid; i < n; i += 256) idx[row * MAXDEG + i] = s_nbr[i];

    grid_dep_wait();

    const float* s2h = s2 + (size_t)head * NNODES;
    float s1i = s1[(size_t)head * NNODES + row];

    float mx = -3.0e38f;
    for (int i = lane; i < n; i += 32) mx = fmaxf(mx, s2h[s_nbr[i]]);
    #pragma unroll
    for (int o = 16; o > 0; o >>= 1) mx = fmaxf(mx, __shfl_xor_sync(0xffffffffu, mx, o));
    float m = lrelu(s1i + mx);

    float zp = 0.f;
    for (int i = lane; i < n; i += 32) {
        float e = lrelu(s1i + s2h[s_nbr[i]]);
        float w = __expf(e - m);
        s_w[head][i] = w;
        zp += w;
    }
    #pragma unroll
    for (int o = 16; o > 0; o >>= 1) zp += __shfl_xor_sync(0xffffffffu, zp, o);
    __syncwarp();

    const __half2* hb = hh + (size_t)head * NNODES * 32;
    float2 acc = make_float2(0.f, 0.f);
    int i = 0;
    for (; i + 3 < n; i += 4) {
        float w0 = s_w[head][i],     w1 = s_w[head][i + 1];
        float w2 = s_w[head][i + 2], w3 = s_w[head][i + 3];
        float2 v0 = __half22float2(hb[(size_t)s_nbr[i]     * 32 + lane]);
        float2 v1 = __half22float2(hb[(size_t)s_nbr[i + 1] * 32 + lane]);
        float2 v2 = __half22float2(hb[(size_t)s_nbr[i + 2] * 32 + lane]);
        float2 v3 = __half22float2(hb[(size_t)s_nbr[i + 3] * 32 + lane]);
        acc.x += w0 * v0.x; acc.y += w0 * v0.y;
        acc.x += w1 * v1.x; acc.y += w1 * v1.y;
        acc.x += w2 * v2.x; acc.y += w2 * v2.y;
        acc.x += w3 * v3.x; acc.y += w3 * v3.y;
    }
    for (; i < n; i++) {
        float w = s_w[head][i];
        float2 v = __half22float2(hb[(size_t)s_nbr[i] * 32 + lane]);
        acc.x += w * v.x; acc.y += w * v.y;
    }

    float inv = 1.f / zp;
    float ox = acc.x * inv, oy = acc.y * inv;
    ox = ox > 0.f ? ox : expm1f(ox);
    oy = oy > 0.f ? oy : expm1f(oy);
    ((float2*)out)[(size_t)row * 256 + head * 32 + lane] = make_float2(ox, oy);
}

// ------- layer2: K=512 split-K x4, grid (32,4) + fused last-block fixup --------
// Partials written per z; last block per m-tile (counter) deterministically sums
// z=0..3, emits fp16 h2 table + layer2 scores, and resets its counter.
__global__ __launch_bounds__(256)
void gemm2_tc(const float* __restrict__ A, const float* __restrict__ B,
              float* __restrict__ part, const float* __restrict__ avec,
              __half* __restrict__ h2h, float* __restrict__ s1,
              float* __restrict__ s2) {
    using namespace nvcuda::wmma;
    grid_dep_wait();
    __shared__ SmemGemm sm;
    int m0 = blockIdx.x * 128;
    int z  = blockIdx.y;
    int warp = threadIdx.x >> 5;
    int wm = warp & 3, wn = warp >> 2;

    CFragH c[2][2];
    #pragma unroll
    for (int fm = 0; fm < 2; fm++)
        #pragma unroll
        for (int fn = 0; fn < 2; fn++) fill_fragment(c[fm][fn], 0.f);

    gemm_core<128>(sm, A, 512, B, m0, z * 128, c);

    float* Cb = part + (size_t)z * NN64;
    #pragma unroll
    for (int fm = 0; fm < 2; fm++)
        #pragma unroll
        for (int fn = 0; fn < 2; fn++)
            store_matrix_sync(&Cb[(size_t)(m0 + wm * 32 + fm * 16) * 64 + wn * 32 + fn * 16],
                              c[fm][fn], 64, mem_row_major);

    // ---- split-K fixup: last block per m-tile reduces all partials ----
    __threadfence();
    __shared__ int s_last;
    if (threadIdx.x == 0) {
        int old = atomicAdd(&g_tilecnt[blockIdx.x], 1);
        s_last = (old == SPLITK - 1);
    }
    __syncthreads();
    if (s_last) {
        int wr   = threadIdx.x >> 5;
        int lane = threadIdx.x & 31;
        for (int rr = wr; rr < 128; rr += 8) {
            int row = m0 + rr;
            size_t o0 = (size_t)row * 64 + lane;
            size_t o1 = o0 + 32;
            float v0 = 0.f, v1 = 0.f;
            #pragma unroll
            for (int zz = 0; zz < SPLITK; zz++) {
                v0 += part[o0 + (size_t)zz * NN64];
                v1 += part[o1 + (size_t)zz * NN64];
            }
            h2h[o0] = __float2half_rn(v0);
            h2h[o1] = __float2half_rn(v1);
            float p1 = v0 * avec[lane] + v1 * avec[lane + 32];
            float p2 = v0 * avec[64 + lane] + v1 * avec[96 + lane];
            #pragma unroll
            for (int o = 16; o > 0; o >>= 1) {
                p1 += __shfl_xor_sync(0xffffffffu, p1, o);
                p2 += __shfl_xor_sync(0xffffffffu, p2, o);
            }
            if (lane == 0) { s1[row] = p1; s2[row] = p2; }
        }
        __syncthreads();
        if (threadIdx.x == 0) g_tilecnt[blockIdx.x] = 0;  // reset for next replay
    }
}

// ---------------- layer2 attention: warp per row, fp16 gather ------------------
__global__ __launch_bounds__(256)
void att2_kernel(const __half2* __restrict__ hh, const float* __restrict__ s1,
                 const float* __restrict__ s2, const int* __restrict__ cnt,
                 const int* __restrict__ idx, float* __restrict__ out) {
    int wr   = threadIdx.x >> 5;     // 8 warps
    int lane = threadIdx.x & 31;
    int row  = blockIdx.x * 8 + wr;

    __shared__ int   s_nbr[8][MAXDEG];
    __shared__ float s_w[8][MAXDEG];

    grid_dep_wait();

    int n = cnt[row];
    const int* ip = idx + row * MAXDEG;
    for (int i = lane; i < n; i += 32) s_nbr[wr][i] = ip[i];
    __syncwarp();

    float s1i = s1[row];

    float mx = -3.0e38f;
    for (int i = lane; i < n; i += 32) mx = fmaxf(mx, s2[s_nbr[wr][i]]);
    #pragma unroll
    for (int o = 16; o > 0; o >>= 1) mx = fmaxf(mx, __shfl_xor_sync(0xffffffffu, mx, o));
    float m = lrelu(s1i + mx);

    float zp = 0.f;
    for (int i = lane; i < n; i += 32) {
        float e = lrelu(s1i + s2[s_nbr[wr][i]]);
        float w = __expf(e - m);
        s_w[wr][i] = w;
        zp += w;
    }
    #pragma unroll
    for (int o = 16; o > 0; o >>= 1) zp += __shfl_xor_sync(0xffffffffu, zp, o);
    __syncwarp();

    float2 acc = make_float2(0.f, 0.f);
    int i = 0;
    for (; i + 3 < n; i += 4) {
        float w0 = s_w[wr][i],     w1 = s_w[wr][i + 1];
        float w2 = s_w[wr][i + 2], w3 = s_w[wr][i + 3];
        float2 v0 = __half22float2(hh[(size_t)s_nbr[wr][i]     * 32 + lane]);
        float2 v1 = __half22float2(hh[(size_t)s_nbr[wr][i + 1] * 32 + lane]);
        float2 v2 = __half22float2(hh[(size_t)s_nbr[wr][i + 2] * 32 + lane]);
        float2 v3 = __half22float2(hh[(size_t)s_nbr[wr][i + 3] * 32 + lane]);
        acc.x += w0 * v0.x; acc.y += w0 * v0.y;
        acc.x += w1 * v1.x; acc.y += w1 * v1.y;
        acc.x += w2 * v2.x; acc.y += w2 * v2.y;
        acc.x += w3 * v3.x; acc.y += w3 * v3.y;
    }
    for (; i < n; i++) {
        float w = s_w[wr][i];
        float2 v = __half22float2(hh[(size_t)s_nbr[wr][i] * 32 + lane]);
        acc.x += w * v.x; acc.y += w * v.y;
    }
    float inv = 1.f / zp;
    ((float2*)out)[(size_t)row * 32 + lane] = make_float2(acc.x * inv, acc.y * inv);
}

// ---------------- launcher ----------------
template <typename... Args>
static void launch_pdl(void (*kern)(Args...), dim3 grid, dim3 block,
                       Args... args) {
    cudaLaunchConfig_t cfg = {};
    cfg.gridDim = grid; cfg.blockDim = block; cfg.stream = 0;
    cudaLaunchAttribute at[1];
    at[0].id = cudaLaunchAttributeProgrammaticStreamSerialization;
    at[0].val.programmaticStreamSerializationAllowed = 1;
    cfg.attrs = at; cfg.numAttrs = 1;
    cudaLaunchKernelEx(&cfg, kern, args...);
}

extern "C" void kernel_launch(void* const* d_in, const int* in_sizes, int n_in,
                              void* d_out, int out_size) {
    const float* features = (const float*)d_in[0];   // [4096, 256]
    const float* adj      = (const float*)d_in[1];   // [4096, 4096]
    const float* W_heads  = (const float*)d_in[2];   // [8, 256, 64]
    const float* a_heads  = (const float*)d_in[3];   // [8, 128, 1]
    const float* W_out    = (const float*)d_in[4];   // [512, 64]
    const float* a_out    = (const float*)d_in[5];   // [128, 1]
    float* out = (float*)d_out;                      // [4096, 64]

    int    *cnt, *idxp;
    float  *s1a, *s2a, *x2, *h2p, *s1b, *s2b;
    __half *h1h, *h2h;
    cudaGetSymbolAddress((void**)&cnt,  g_cnt);
    cudaGetSymbolAddress((void**)&idxp, g_idx);
    cudaGetSymbolAddress((void**)&h1h,  g_h1h);
    cudaGetSymbolAddress((void**)&s1a,  g_s1a);
    cudaGetSymbolAddress((void**)&s2a,  g_s2a);
    cudaGetSymbolAddress((void**)&x2,   g_x2);
    cudaGetSymbolAddress((void**)&h2p,  g_h2p);
    cudaGetSymbolAddress((void**)&h2h,  g_h2h);
    cudaGetSymbolAddress((void**)&s1b,  g_s1b);
    cudaGetSymbolAddress((void**)&s2b,  g_s2b);

    // 1. layer1 GEMM (fp16 2-way split MMA) + fused scores + fp16 table
    gemm1_tc<<<dim3(32, 1, 8), 256>>>(features, W_heads, h1h, a_heads, s1a, s2a);

    // 2. layer1 attention with fused CSR build (adj scan overlaps gemm1 via PDL)
    launch_pdl(att1_csr, dim3(NNODES), dim3(256),
               adj, (const __half2*)h1h, (const float*)s1a, (const float*)s2a,
               cnt, idxp, x2);

    // 3. layer2 GEMM (fp16 2-way split, split-K x4) + fused fixup/scores/h2h
    launch_pdl(gemm2_tc, dim3(32, SPLITK, 1), dim3(256),
               (const float*)x2, W_out, h2p, (const float*)a_out, h2h, s1b, s2b);

    // 4. layer2 attention
    launch_pdl(att2_kernel, dim3(NNODES / 8), dim3(256),
               (const __half2*)h2h, (const float*)s1b, (const float*)s2b,
               (const int*)cnt, (const int*)idxp, out);
}

// round 16
// speedup vs baseline: 1.0774x; 1.0774x over previous
#include <cuda_runtime.h>
#include <cuda_fp16.h>
#include <mma.h>
#include <math.h>

#define NNODES 4096
#define MAXDEG 256
#define ALPHA  0.2f
#define NN64   ((size_t)NNODES * 64)

// ---------------- scratch (no allocations allowed) ----------------
__device__ int    g_cnt[NNODES];
__device__ int    g_idx[NNODES * MAXDEG];
__device__ __half g_h1h[8 * NNODES * 64];   // layer1 features, fp16 gather table
__device__ float  g_s1a[8 * NNODES];
__device__ float  g_s2a[8 * NNODES];
__device__ float  g_x2 [NNODES * 512];      // elu(hp) fp32 (GEMM2 input)
__device__ float  g_h2p[8 * NNODES * 64];   // layer2 split-K partials
__device__ __half g_h2h[NNODES * 64];       // layer2 features, fp16 gather table
__device__ float  g_s1b[NNODES];
__device__ float  g_s2b[NNODES];

__device__ __forceinline__ float lrelu(float x) { return x > 0.f ? x : ALPHA * x; }
__device__ __forceinline__ void grid_dep_wait() {
    asm volatile("griddepcontrol.wait;" ::: "memory");
}

// ------ fp16 2-way-split GEMM core: 128x64 tile, 8 warps (4m x 2n of 32x32) ----
// x = hi + lo (both fp16); a*b = ah*bh + ah*bl + al*bh (al*bl ~2^-22, dropped).
struct SmemGemm {
    union {
        struct {
            __half AsH[128][40];
            __half AsL[128][40];
            __half BsH[32][72];
            __half BsL[32][72];
        };
        float Cs[128][68];
    };
};

using AFragH = nvcuda::wmma::fragment<nvcuda::wmma::matrix_a, 16, 16, 16,
                                      __half, nvcuda::wmma::row_major>;
using BFragH = nvcuda::wmma::fragment<nvcuda::wmma::matrix_b, 16, 16, 16,
                                      __half, nvcuda::wmma::row_major>;
using CFragH = nvcuda::wmma::fragment<nvcuda::wmma::accumulator, 16, 16, 16, float>;

__device__ __forceinline__ void split_h(float x, __half* hi, __half* lo) {
    __half h = __float2half_rn(x);
    *hi = h;
    *lo = __float2half_rn(x - __half2float(h));
}

template <int KLEN>
__device__ __forceinline__ void gemm_core(SmemGemm& sm, const float* __restrict__ A,
                                          int lda, const float* __restrict__ Bb,
                                          int m0, int kb0, CFragH c[2][2]) {
    using namespace nvcuda::wmma;
    int tid = threadIdx.x;
    int warp = tid >> 5;
    int wm = warp & 3, wn = warp >> 2;
    int ar = tid >> 1, ac = (tid & 1) * 16;     // A: 128 rows x 32 cols, 16 f/thread
    int br = tid >> 3, bc = (tid & 7) * 8;      // B: 32 rows x 64 cols, 8 f/thread

    for (int kb = kb0; kb < kb0 + KLEN; kb += 32) {
        const float* Ag = A + (size_t)(m0 + ar) * lda + kb + ac;
        float av[16];
        *(float4*)&av[0]  = *(const float4*)(Ag + 0);
        *(float4*)&av[4]  = *(const float4*)(Ag + 4);
        *(float4*)&av[8]  = *(const float4*)(Ag + 8);
        *(float4*)&av[12] = *(const float4*)(Ag + 12);
        const float* Bg = Bb + (size_t)(kb + br) * 64 + bc;
        float bv[8];
        *(float4*)&bv[0] = *(const float4*)(Bg + 0);
        *(float4*)&bv[4] = *(const float4*)(Bg + 4);

        #pragma unroll
        for (int e = 0; e < 16; e++)
            split_h(av[e], &sm.AsH[ar][ac + e], &sm.AsL[ar][ac + e]);
        #pragma unroll
        for (int e = 0; e < 8; e++)
            split_h(bv[e], &sm.BsH[br][bc + e], &sm.BsL[br][bc + e]);
        __syncthreads();

        #pragma unroll
        for (int k = 0; k < 32; k += 16) {
            AFragH ah[2], al[2];
            BFragH bh[2], bl[2];
            #pragma unroll
            for (int f = 0; f < 2; f++) {
                load_matrix_sync(ah[f], &sm.AsH[wm * 32 + f * 16][k], 40);
                load_matrix_sync(al[f], &sm.AsL[wm * 32 + f * 16][k], 40);
                load_matrix_sync(bh[f], &sm.BsH[k][wn * 32 + f * 16], 72);
                load_matrix_sync(bl[f], &sm.BsL[k][wn * 32 + f * 16], 72);
            }
            #pragma unroll
            for (int fm = 0; fm < 2; fm++)
                #pragma unroll
                for (int fn = 0; fn < 2; fn++) {
                    mma_sync(c[fm][fn], al[fm], bh[fn], c[fm][fn]);
                    mma_sync(c[fm][fn], ah[fm], bl[fn], c[fm][fn]);
                    mma_sync(c[fm][fn], ah[fm], bh[fn], c[fm][fn]);
                }
        }
        __syncthreads();
    }
}

// ------- layer1: K=256, grid (32,1,8); fused scores + fp16 table epilogue ------
__global__ __launch_bounds__(256)
void gemm1_tc(const float* __restrict__ A, const float* __restrict__ B,
              __half* __restrict__ Ch, const float* __restrict__ avec,
              float* __restrict__ s1, float* __restrict__ s2) {
    using namespace nvcuda::wmma;
    __shared__ SmemGemm sm;
    int m0 = blockIdx.x * 128;
    int hd = blockIdx.z;
    int warp = threadIdx.x >> 5;
    int wm = warp & 3, wn = warp >> 2;

    CFragH c[2][2];
    #pragma unroll
    for (int fm = 0; fm < 2; fm++)
        #pragma unroll
        for (int fn = 0; fn < 2; fn++) fill_fragment(c[fm][fn], 0.f);

    gemm_core<256>(sm, A, 256, B + (size_t)hd * 256 * 64, m0, 0, c);

    #pragma unroll
    for (int fm = 0; fm < 2; fm++)
        #pragma unroll
        for (int fn = 0; fn < 2; fn++)
            store_matrix_sync(&sm.Cs[wm * 32 + fm * 16][wn * 32 + fn * 16],
                              c[fm][fn], 68, mem_row_major);
    __syncthreads();

    // fp16 gather table: 128 rows x 32 half2
    __half2* Hb = (__half2*)(Ch + (size_t)hd * NN64);
    for (int idx = threadIdx.x; idx < 128 * 32; idx += 256) {
        int r = idx >> 5, d2 = idx & 31;
        Hb[(size_t)(m0 + r) * 32 + d2] =
            __floats2half2_rn(sm.Cs[r][d2 * 2], sm.Cs[r][d2 * 2 + 1]);
    }
    // fused scores: thread per row
    if (threadIdx.x < 128) {
        int r = threadIdx.x;
        const float* a1 = avec + hd * 128;
        float p1 = 0.f, p2 = 0.f;
        #pragma unroll
        for (int d = 0; d < 64; d++) {
            float v = sm.Cs[r][d];
            p1 += v * a1[d];
            p2 += v * a1[64 + d];
        }
        s1[(size_t)hd * NNODES + m0 + r] = p1;
        s2[(size_t)hd * NNODES + m0 + r] = p2;
    }
}

// ------- layer1 attention + fused CSR build: block=row, warp=head --------------
__global__ __launch_bounds__(256)
void att1_csr(const float* __restrict__ adj, const __half2* __restrict__ hh,
              const float* __restrict__ s1, const float* __restrict__ s2,
              int* __restrict__ cnt, int* __restrict__ idx,
              float* __restrict__ out) {
    int row  = blockIdx.x;
    int tid  = threadIdx.x;       // 256
    int head = tid >> 5;
    int lane = tid & 31;

    __shared__ int   s_nbr[MAXDEG];
    __shared__ int   s_cnt;
    __shared__ float s_w[8][MAXDEG];

    // CSR scan of this row (independent of gemm1; overlaps it via PDL)
    if (tid == 0) s_cnt = 0;
    __syncthreads();
    const float4* r = (const float4*)(adj + (size_t)row * NNODES);
    for (int c = tid; c < NNODES / 4; c += 256) {
        float4 v = r[c];
        if (v.x > 0.f) { int p = atomicAdd(&s_cnt, 1); if (p < MAXDEG) s_nbr[p] = c * 4 + 0; }
        if (v.y > 0.f) { int p = atomicAdd(&s_cnt, 1); if (p < MAXDEG) s_nbr[p] = c * 4 + 1; }
        if (v.z > 0.f) { int p = atomicAdd(&s_cnt, 1); if (p < MAXDEG) s_nbr[p] = c * 4 + 2; }
        if (v.w > 0.f) { int p = atomicAdd(&s_cnt, 1); if (p < MAXDEG) s_nbr[p] = c * 4 + 3; }
    }
    __syncthreads();
    int n = min(s_cnt, MAXDEG);
    if (tid == 0) cnt[row] = n;
    for (int i = tid; i < n; i += 256) idx[row * MAXDEG + i] = s_nbr[i];

    grid_dep_wait();

    const float* s2h = s2 + (size_t)head * NNODES;
    float s1i = s1[(size_t)head * NNODES + row];

    float mx = -3.0e38f;
    for (int i = lane; i < n; i += 32) mx = fmaxf(mx, s2h[s_nbr[i]]);
    #pragma unroll
    for (int o = 16; o > 0; o >>= 1) mx = fmaxf(mx, __shfl_xor_sync(0xffffffffu, mx, o));
    float m = lrelu(s1i + mx);

    float zp = 0.f;
    for (int i = lane; i < n; i += 32) {
        float e = lrelu(s1i + s2h[s_nbr[i]]);
        float w = __expf(e - m);
        s_w[head][i] = w;
        zp += w;
    }
    #pragma unroll
    for (int o = 16; o > 0; o >>= 1) zp += __shfl_xor_sync(0xffffffffu, zp, o);
    __syncwarp();

    // gather with 8-deep MLP
    const __half2* hb = hh + (size_t)head * NNODES * 32;
    float2 acc = make_float2(0.f, 0.f);
    int i = 0;
    for (; i + 7 < n; i += 8) {
        float2 v[8];
        float w[8];
        #pragma unroll
        for (int u = 0; u < 8; u++) {
            w[u] = s_w[head][i + u];
            v[u] = __half22float2(hb[(size_t)s_nbr[i + u] * 32 + lane]);
        }
        #pragma unroll
        for (int u = 0; u < 8; u++) { acc.x += w[u] * v[u].x; acc.y += w[u] * v[u].y; }
    }
    for (; i < n; i++) {
        float w = s_w[head][i];
        float2 v = __half22float2(hb[(size_t)s_nbr[i] * 32 + lane]);
        acc.x += w * v.x; acc.y += w * v.y;
    }

    float inv = 1.f / zp;
    float ox = acc.x * inv, oy = acc.y * inv;
    ox = ox > 0.f ? ox : expm1f(ox);
    oy = oy > 0.f ? oy : expm1f(oy);
    ((float2*)out)[(size_t)row * 256 + head * 32 + lane] = make_float2(ox, oy);
}

// ------- layer2: K=512 split-K x8, grid (32,8); fp32 partial epilogue ----------
__global__ __launch_bounds__(256)
void gemm2_tc(const float* __restrict__ A, const float* __restrict__ B,
              float* __restrict__ part) {
    using namespace nvcuda::wmma;
    grid_dep_wait();
    __shared__ SmemGemm sm;
    int m0 = blockIdx.x * 128;
    int z  = blockIdx.y;
    int warp = threadIdx.x >> 5;
    int wm = warp & 3, wn = warp >> 2;

    CFragH c[2][2];
    #pragma unroll
    for (int fm = 0; fm < 2; fm++)
        #pragma unroll
        for (int fn = 0; fn < 2; fn++) fill_fragment(c[fm][fn], 0.f);

    gemm_core<64>(sm, A, 512, B, m0, z * 64, c);

    float* Cb = part + (size_t)z * NN64;
    #pragma unroll
    for (int fm = 0; fm < 2; fm++)
        #pragma unroll
        for (int fn = 0; fn < 2; fn++)
            store_matrix_sync(&Cb[(size_t)(m0 + wm * 32 + fm * 16) * 64 + wn * 32 + fn * 16],
                              c[fm][fn], 64, mem_row_major);
}

// ---------------- layer2 reduce partials + scores + fp16 table (warp/row) ------
__global__ __launch_bounds__(256)
void reduce_scores2(const float* __restrict__ part, const float* __restrict__ a,
                    __half* __restrict__ h2h, float* __restrict__ s1,
                    float* __restrict__ s2) {
    grid_dep_wait();
    int wr   = threadIdx.x >> 5;
    int lane = threadIdx.x & 31;
    int row  = blockIdx.x * 8 + wr;
    size_t o0 = (size_t)row * 64 + lane;
    size_t o1 = o0 + 32;
    float v0 = 0.f, v1 = 0.f;
    #pragma unroll
    for (int z = 0; z < 8; z++) {
        v0 += part[o0 + (size_t)z * NN64];
        v1 += part[o1 + (size_t)z * NN64];
    }
    h2h[o0] = __float2half_rn(v0);
    h2h[o1] = __float2half_rn(v1);
    float p1 = v0 * a[lane] + v1 * a[lane + 32];
    float p2 = v0 * a[64 + lane] + v1 * a[96 + lane];
    #pragma unroll
    for (int o = 16; o > 0; o >>= 1) {
        p1 += __shfl_xor_sync(0xffffffffu, p1, o);
        p2 += __shfl_xor_sync(0xffffffffu, p2, o);
    }
    if (lane == 0) { s1[row] = p1; s2[row] = p2; }
}

// ------- layer2 attention: warp-pair per row (parity split), fp16 gather -------
__global__ __launch_bounds__(256)
void att2_kernel(const __half2* __restrict__ hh, const float* __restrict__ s1,
                 const float* __restrict__ s2, const int* __restrict__ cnt,
                 const int* __restrict__ idx, float* __restrict__ out) {
    int warp = threadIdx.x >> 5;     // 8 warps = 4 rows x 2 subwarps
    int wr   = warp >> 1;
    int sub  = warp & 1;
    int lane = threadIdx.x & 31;
    int row  = blockIdx.x * 4 + wr;
    int t64  = sub * 32 + lane;

    __shared__ int    s_nbr[4][MAXDEG];
    __shared__ float  s_w[4][MAXDEG];
    __shared__ float  s_red[4][2];
    __shared__ float  s_z[4][2];
    __shared__ float2 s_acc[4][32];

    grid_dep_wait();

    int n = cnt[row];
    const int* ip = idx + row * MAXDEG;
    for (int i = t64; i < n; i += 64) s_nbr[wr][i] = ip[i];
    __syncthreads();

    float s1i = s1[row];

    float mx = -3.0e38f;
    for (int i = t64; i < n; i += 64) mx = fmaxf(mx, s2[s_nbr[wr][i]]);
    #pragma unroll
    for (int o = 16; o > 0; o >>= 1) mx = fmaxf(mx, __shfl_xor_sync(0xffffffffu, mx, o));
    if (lane == 0) s_red[wr][sub] = mx;
    __syncthreads();
    mx = fmaxf(s_red[wr][0], s_red[wr][1]);
    float m = lrelu(s1i + mx);

    float zp = 0.f;
    for (int i = t64; i < n; i += 64) {
        float e = lrelu(s1i + s2[s_nbr[wr][i]]);
        float w = __expf(e - m);
        s_w[wr][i] = w;
        zp += w;
    }
    #pragma unroll
    for (int o = 16; o > 0; o >>= 1) zp += __shfl_xor_sync(0xffffffffu, zp, o);
    if (lane == 0) s_z[wr][sub] = zp;
    __syncthreads();
    float Z = s_z[wr][0] + s_z[wr][1];

    // gather: subwarp takes its parity; unroll 4 (stride 2 -> spans 8 indices)
    float2 acc = make_float2(0.f, 0.f);
    int i = sub;
    for (; i + 6 < n; i += 8) {
        float w0 = s_w[wr][i],     w1 = s_w[wr][i + 2];
        float w2 = s_w[wr][i + 4], w3 = s_w[wr][i + 6];
        float2 v0 = __half22float2(hh[(size_t)s_nbr[wr][i]     * 32 + lane]);
        float2 v1 = __half22float2(hh[(size_t)s_nbr[wr][i + 2] * 32 + lane]);
        float2 v2 = __half22float2(hh[(size_t)s_nbr[wr][i + 4] * 32 + lane]);
        float2 v3 = __half22float2(hh[(size_t)s_nbr[wr][i + 6] * 32 + lane]);
        acc.x += w0 * v0.x; acc.y += w0 * v0.y;
        acc.x += w1 * v1.x; acc.y += w1 * v1.y;
        acc.x += w2 * v2.x; acc.y += w2 * v2.y;
        acc.x += w3 * v3.x; acc.y += w3 * v3.y;
    }
    for (; i < n; i += 2) {
        float w = s_w[wr][i];
        float2 v = __half22float2(hh[(size_t)s_nbr[wr][i] * 32 + lane]);
        acc.x += w * v.x; acc.y += w * v.y;
    }
    if (sub == 1) s_acc[wr][lane] = acc;
    __syncthreads();
    if (sub == 0) {
        float2 o2 = s_acc[wr][lane];
        float inv = 1.f / Z;
        ((float2*)out)[(size_t)row * 32 + lane] =
            make_float2((acc.x + o2.x) * inv, (acc.y + o2.y) * inv);
    }
}

// ---------------- launcher ----------------
template <typename... Args>
static void launch_pdl(void (*kern)(Args...), dim3 grid, dim3 block,
                       Args... args) {
    cudaLaunchConfig_t cfg = {};
    cfg.gridDim = grid; cfg.blockDim = block; cfg.stream = 0;
    cudaLaunchAttribute at[1];
    at[0].id = cudaLaunchAttributeProgrammaticStreamSerialization;
    at[0].val.programmaticStreamSerializationAllowed = 1;
    cfg.attrs = at; cfg.numAttrs = 1;
    cudaLaunchKernelEx(&cfg, kern, args...);
}

extern "C" void kernel_launch(void* const* d_in, const int* in_sizes, int n_in,
                              void* d_out, int out_size) {
    const float* features = (const float*)d_in[0];   // [4096, 256]
    const float* adj      = (const float*)d_in[1];   // [4096, 4096]
    const float* W_heads  = (const float*)d_in[2];   // [8, 256, 64]
    const float* a_heads  = (const float*)d_in[3];   // [8, 128, 1]
    const float* W_out    = (const float*)d_in[4];   // [512, 64]
    const float* a_out    = (const float*)d_in[5];   // [128, 1]
    float* out = (float*)d_out;                      // [4096, 64]

    int    *cnt, *idxp;
    float  *s1a, *s2a, *x2, *h2p, *s1b, *s2b;
    __half *h1h, *h2h;
    cudaGetSymbolAddress((void**)&cnt,  g_cnt);
    cudaGetSymbolAddress((void**)&idxp, g_idx);
    cudaGetSymbolAddress((void**)&h1h,  g_h1h);
    cudaGetSymbolAddress((void**)&s1a,  g_s1a);
    cudaGetSymbolAddress((void**)&s2a,  g_s2a);
    cudaGetSymbolAddress((void**)&x2,   g_x2);
    cudaGetSymbolAddress((void**)&h2p,  g_h2p);
    cudaGetSymbolAddress((void**)&h2h,  g_h2h);
    cudaGetSymbolAddress((void**)&s1b,  g_s1b);
    cudaGetSymbolAddress((void**)&s2b,  g_s2b);

    // 1. layer1 GEMM (fp16 2-way split MMA) + fused scores + fp16 table
    gemm1_tc<<<dim3(32, 1, 8), 256>>>(features, W_heads, h1h, a_heads, s1a, s2a);

    // 2. layer1 attention with fused CSR build (adj scan overlaps gemm1 via PDL)
    launch_pdl(att1_csr, dim3(NNODES), dim3(256),
               adj, (const __half2*)h1h, (const float*)s1a, (const float*)s2a,
               cnt, idxp, x2);

    // 3. layer2 GEMM (fp16 2-way split, split-K x8 -> 256 blocks)
    launch_pdl(gemm2_tc, dim3(32, 8, 1), dim3(256),
               (const float*)x2, W_out, h2p);

    // 4. reduce partials + layer2 scores + fp16 table
    launch_pdl(reduce_scores2, dim3(NNODES / 8), dim3(256),
               (const float*)h2p, a_out, h2h, s1b, s2b);

    // 5. layer2 attention (warp-pair per row)
    launch_pdl(att2_kernel, dim3(NNODES / 4), dim3(256),
               (const __half2*)h2h, (const float*)s1b, (const float*)s2b,
               (const int*)cnt, (const int*)idxp, out);
}

// round 17
// speedup vs baseline: 1.1980x; 1.1119x over previous
#include <cuda_runtime.h>
#include <cuda_fp16.h>
#include <mma.h>
#include <math.h>

#define NNODES 4096
#define MAXDEG 256
#define ALPHA  0.2f
#define NN64   ((size_t)NNODES * 64)
#define SPLITK 4

// ---------------- scratch (no allocations allowed) ----------------
__device__ int    g_cnt[NNODES];
__device__ int    g_idx[NNODES * MAXDEG];
__device__ __half g_h1h[8 * NNODES * 64];   // layer1 features, fp16 gather table
__device__ float  g_s1a[8 * NNODES];
__device__ float  g_s2a[8 * NNODES];
__device__ float  g_x2 [NNODES * 512];      // elu(hp) fp32 (GEMM2 input)
__device__ float  g_h2p[SPLITK * NNODES * 64]; // layer2 split-K partials
__device__ __half g_h2h[NNODES * 64];       // layer2 features, fp16 gather table
__device__ float  g_s1b[NNODES];
__device__ float  g_s2b[NNODES];

__device__ __forceinline__ float lrelu(float x) { return x > 0.f ? x : ALPHA * x; }
__device__ __forceinline__ void grid_dep_wait() {
    asm volatile("griddepcontrol.wait;" ::: "memory");
}

// ------ fp16 2-TERM split GEMM core: 128x64 tile, 8 warps (4m x 2n of 32x32) ---
// A rounded to fp16 (ah); B split b = bh + bl. a*b ~= ah*bh + ah*bl.
// Dropped al*b term ~2.8e-4 RMS relative. 2 MMAs + 3 frag loads per pair (vs 3+4).
struct SmemGemm {
    union {
        struct {
            __half AsH[128][40];
            __half BsH[32][72];
            __half BsL[32][72];
        };
        float Cs[128][68];
    };
};

using AFragH = nvcuda::wmma::fragment<nvcuda::wmma::matrix_a, 16, 16, 16,
                                      __half, nvcuda::wmma::row_major>;
using BFragH = nvcuda::wmma::fragment<nvcuda::wmma::matrix_b, 16, 16, 16,
                                      __half, nvcuda::wmma::row_major>;
using CFragH = nvcuda::wmma::fragment<nvcuda::wmma::accumulator, 16, 16, 16, float>;

__device__ __forceinline__ void split_h(float x, __half* hi, __half* lo) {
    __half h = __float2half_rn(x);
    *hi = h;
    *lo = __float2half_rn(x - __half2float(h));
}

template <int KLEN>
__device__ __forceinline__ void gemm_core(SmemGemm& sm, const float* __restrict__ A,
                                          int lda, const float* __restrict__ Bb,
                                          int m0, int kb0, CFragH c[2][2]) {
    using namespace nvcuda::wmma;
    int tid = threadIdx.x;
    int warp = tid >> 5;
    int wm = warp & 3, wn = warp >> 2;
    int ar = tid >> 1, ac = (tid & 1) * 16;     // A: 128 rows x 32 cols, 16 f/thread
    int br = tid >> 3, bc = (tid & 7) * 8;      // B: 32 rows x 64 cols, 8 f/thread

    for (int kb = kb0; kb < kb0 + KLEN; kb += 32) {
        const float* Ag = A + (size_t)(m0 + ar) * lda + kb + ac;
        float av[16];
        *(float4*)&av[0]  = *(const float4*)(Ag + 0);
        *(float4*)&av[4]  = *(const float4*)(Ag + 4);
        *(float4*)&av[8]  = *(const float4*)(Ag + 8);
        *(float4*)&av[12] = *(const float4*)(Ag + 12);
        const float* Bg = Bb + (size_t)(kb + br) * 64 + bc;
        float bv[8];
        *(float4*)&bv[0] = *(const float4*)(Bg + 0);
        *(float4*)&bv[4] = *(const float4*)(Bg + 4);

        #pragma unroll
        for (int e = 0; e < 16; e++)
            sm.AsH[ar][ac + e] = __float2half_rn(av[e]);
        #pragma unroll
        for (int e = 0; e < 8; e++)
            split_h(bv[e], &sm.BsH[br][bc + e], &sm.BsL[br][bc + e]);
        __syncthreads();

        #pragma unroll
        for (int k = 0; k < 32; k += 16) {
            AFragH ah[2];
            BFragH bh[2], bl[2];
            #pragma unroll
            for (int f = 0; f < 2; f++) {
                load_matrix_sync(ah[f], &sm.AsH[wm * 32 + f * 16][k], 40);
                load_matrix_sync(bh[f], &sm.BsH[k][wn * 32 + f * 16], 72);
                load_matrix_sync(bl[f], &sm.BsL[k][wn * 32 + f * 16], 72);
            }
            #pragma unroll
            for (int fm = 0; fm < 2; fm++)
                #pragma unroll
                for (int fn = 0; fn < 2; fn++) {
                    mma_sync(c[fm][fn], ah[fm], bl[fn], c[fm][fn]);
                    mma_sync(c[fm][fn], ah[fm], bh[fn], c[fm][fn]);
                }
        }
        __syncthreads();
    }
}

// ------- layer1: K=256, grid (32,1,8); fused scores + fp16 table epilogue ------
__global__ __launch_bounds__(256)
void gemm1_tc(const float* __restrict__ A, const float* __restrict__ B,
              __half* __restrict__ Ch, const float* __restrict__ avec,
              float* __restrict__ s1, float* __restrict__ s2) {
    using namespace nvcuda::wmma;
    __shared__ SmemGemm sm;
    int m0 = blockIdx.x * 128;
    int hd = blockIdx.z;
    int warp = threadIdx.x >> 5;
    int wm = warp & 3, wn = warp >> 2;

    CFragH c[2][2];
    #pragma unroll
    for (int fm = 0; fm < 2; fm++)
        #pragma unroll
        for (int fn = 0; fn < 2; fn++) fill_fragment(c[fm][fn], 0.f);

    gemm_core<256>(sm, A, 256, B + (size_t)hd * 256 * 64, m0, 0, c);

    #pragma unroll
    for (int fm = 0; fm < 2; fm++)
        #pragma unroll
        for (int fn = 0; fn < 2; fn++)
            store_matrix_sync(&sm.Cs[wm * 32 + fm * 16][wn * 32 + fn * 16],
                              c[fm][fn], 68, mem_row_major);
    __syncthreads();

    // fp16 gather table: 128 rows x 32 half2
    __half2* Hb = (__half2*)(Ch + (size_t)hd * NN64);
    for (int idx = threadIdx.x; idx < 128 * 32; idx += 256) {
        int r = idx >> 5, d2 = idx & 31;
        Hb[(size_t)(m0 + r) * 32 + d2] =
            __floats2half2_rn(sm.Cs[r][d2 * 2], sm.Cs[r][d2 * 2 + 1]);
    }
    // fused scores: thread per row
    if (threadIdx.x < 128) {
        int r = threadIdx.x;
        const float* a1 = avec + hd * 128;
        float p1 = 0.f, p2 = 0.f;
        #pragma unroll
        for (int d = 0; d < 64; d++) {
            float v = sm.Cs[r][d];
            p1 += v * a1[d];
            p2 += v * a1[64 + d];
        }
        s1[(size_t)hd * NNODES + m0 + r] = p1;
        s2[(size_t)hd * NNODES + m0 + r] = p2;
    }
}

// ------- layer1 attention + fused CSR build: block=row, warp=head --------------
__global__ __launch_bounds__(256)
void att1_csr(const float* __restrict__ adj, const __half2* __restrict__ hh,
              const float* __restrict__ s1, const float* __restrict__ s2,
              int* __restrict__ cnt, int* __restrict__ idx,
              float* __restrict__ out) {
    int row  = blockIdx.x;
    int tid  = threadIdx.x;       // 256
    int head = tid >> 5;
    int lane = tid & 31;

    __shared__ int   s_nbr[MAXDEG];
    __shared__ int   s_cnt;
    __shared__ float s_w[8][MAXDEG];

    // CSR scan of this row (independent of gemm1; overlaps it via PDL)
    if (tid == 0) s_cnt = 0;
    __syncthreads();
    const float4* r = (const float4*)(adj + (size_t)row * NNODES);
    for (int c = tid; c < NNODES / 4; c += 256) {
        float4 v = r[c];
        if (v.x > 0.f) { int p = atomicAdd(&s_cnt, 1); if (p < MAXDEG) s_nbr[p] = c * 4 + 0; }
        if (v.y > 0.f) { int p = atomicAdd(&s_cnt, 1); if (p < MAXDEG) s_nbr[p] = c * 4 + 1; }
        if (v.z > 0.f) { int p = atomicAdd(&s_cnt, 1); if (p < MAXDEG) s_nbr[p] = c * 4 + 2; }
        if (v.w > 0.f) { int p = atomicAdd(&s_cnt, 1); if (p < MAXDEG) s_nbr[p] = c * 4 + 3; }
    }
    __syncthreads();
    int n = min(s_cnt, MAXDEG);
    if (tid == 0) cnt[row] = n;
    for (int i = tid; i < n; i += 256) idx[row * MAXDEG + i] = s_nbr[i];

    grid_dep_wait();

    const float* s2h = s2 + (size_t)head * NNODES;
    float s1i = s1[(size_t)head * NNODES + row];

    float mx = -3.0e38f;
    for (int i = lane; i < n; i += 32) mx = fmaxf(mx, s2h[s_nbr[i]]);
    #pragma unroll
    for (int o = 16; o > 0; o >>= 1) mx = fmaxf(mx, __shfl_xor_sync(0xffffffffu, mx, o));
    float m = lrelu(s1i + mx);

    float zp = 0.f;
    for (int i = lane; i < n; i += 32) {
        float e = lrelu(s1i + s2h[s_nbr[i]]);
        float w = __expf(e - m);
        s_w[head][i] = w;
        zp += w;
    }
    #pragma unroll
    for (int o = 16; o > 0; o >>= 1) zp += __shfl_xor_sync(0xffffffffu, zp, o);
    __syncwarp();

    const __half2* hb = hh + (size_t)head * NNODES * 32;
    float2 acc = make_float2(0.f, 0.f);
    int i = 0;
    for (; i + 3 < n; i += 4) {
        float w0 = s_w[head][i],     w1 = s_w[head][i + 1];
        float w2 = s_w[head][i + 2], w3 = s_w[head][i + 3];
        float2 v0 = __half22float2(hb[(size_t)s_nbr[i]     * 32 + lane]);
        float2 v1 = __half22float2(hb[(size_t)s_nbr[i + 1] * 32 + lane]);
        float2 v2 = __half22float2(hb[(size_t)s_nbr[i + 2] * 32 + lane]);
        float2 v3 = __half22float2(hb[(size_t)s_nbr[i + 3] * 32 + lane]);
        acc.x += w0 * v0.x; acc.y += w0 * v0.y;
        acc.x += w1 * v1.x; acc.y += w1 * v1.y;
        acc.x += w2 * v2.x; acc.y += w2 * v2.y;
        acc.x += w3 * v3.x; acc.y += w3 * v3.y;
    }
    for (; i < n; i++) {
        float w = s_w[head][i];
        float2 v = __half22float2(hb[(size_t)s_nbr[i] * 32 + lane]);
        acc.x += w * v.x; acc.y += w * v.y;
    }

    float inv = 1.f / zp;
    float ox = acc.x * inv, oy = acc.y * inv;
    ox = ox > 0.f ? ox : expm1f(ox);
    oy = oy > 0.f ? oy : expm1f(oy);
    ((float2*)out)[(size_t)row * 256 + head * 32 + lane] = make_float2(ox, oy);
}

// ------- layer2: K=512 split-K x4, grid (32,4); fp32 partial epilogue ----------
__global__ __launch_bounds__(256)
void gemm2_tc(const float* __restrict__ A, const float* __restrict__ B,
              float* __restrict__ part) {
    using namespace nvcuda::wmma;
    grid_dep_wait();
    __shared__ SmemGemm sm;
    int m0 = blockIdx.x * 128;
    int z  = blockIdx.y;
    int warp = threadIdx.x >> 5;
    int wm = warp & 3, wn = warp >> 2;

    CFragH c[2][2];
    #pragma unroll
    for (int fm = 0; fm < 2; fm++)
        #pragma unroll
        for (int fn = 0; fn < 2; fn++) fill_fragment(c[fm][fn], 0.f);

    gemm_core<128>(sm, A, 512, B, m0, z * 128, c);

    float* Cb = part + (size_t)z * NN64;
    #pragma unroll
    for (int fm = 0; fm < 2; fm++)
        #pragma unroll
        for (int fn = 0; fn < 2; fn++)
            store_matrix_sync(&Cb[(size_t)(m0 + wm * 32 + fm * 16) * 64 + wn * 32 + fn * 16],
                              c[fm][fn], 64, mem_row_major);
}

// ---------------- layer2 reduce partials + scores + fp16 table (warp/row) ------
__global__ __launch_bounds__(256)
void reduce_scores2(const float* __restrict__ part, const float* __restrict__ a,
                    __half* __restrict__ h2h, float* __restrict__ s1,
                    float* __restrict__ s2) {
    grid_dep_wait();
    int wr   = threadIdx.x >> 5;
    int lane = threadIdx.x & 31;
    int row  = blockIdx.x * 8 + wr;
    size_t o0 = (size_t)row * 64 + lane;
    size_t o1 = o0 + 32;
    float v0 = 0.f, v1 = 0.f;
    #pragma unroll
    for (int z = 0; z < SPLITK; z++) {
        v0 += part[o0 + (size_t)z * NN64];
        v1 += part[o1 + (size_t)z * NN64];
    }
    h2h[o0] = __float2half_rn(v0);
    h2h[o1] = __float2half_rn(v1);
    float p1 = v0 * a[lane] + v1 * a[lane + 32];
    float p2 = v0 * a[64 + lane] + v1 * a[96 + lane];
    #pragma unroll
    for (int o = 16; o > 0; o >>= 1) {
        p1 += __shfl_xor_sync(0xffffffffu, p1, o);
        p2 += __shfl_xor_sync(0xffffffffu, p2, o);
    }
    if (lane == 0) { s1[row] = p1; s2[row] = p2; }
}

// ---------------- layer2 attention: warp per row, fp16 gather ------------------
__global__ __launch_bounds__(256)
void att2_kernel(const __half2* __restrict__ hh, const float* __restrict__ s1,
                 const float* __restrict__ s2, const int* __restrict__ cnt,
                 const int* __restrict__ idx, float* __restrict__ out) {
    int wr   = threadIdx.x >> 5;     // 8 warps
    int lane = threadIdx.x & 31;
    int row  = blockIdx.x * 8 + wr;

    __shared__ int   s_nbr[8][MAXDEG];
    __shared__ float s_w[8][MAXDEG];

    grid_dep_wait();

    int n = cnt[row];
    const int* ip = idx + row * MAXDEG;
    for (int i = lane; i < n; i += 32) s_nbr[wr][i] = ip[i];
    __syncwarp();

    float s1i = s1[row];

    float mx = -3.0e38f;
    for (int i = lane; i < n; i += 32) mx = fmaxf(mx, s2[s_nbr[wr][i]]);
    #pragma unroll
    for (int o = 16; o > 0; o >>= 1) mx = fmaxf(mx, __shfl_xor_sync(0xffffffffu, mx, o));
    float m = lrelu(s1i + mx);

    float zp = 0.f;
    for (int i = lane; i < n; i += 32) {
        float e = lrelu(s1i + s2[s_nbr[wr][i]]);
        float w = __expf(e - m);
        s_w[wr][i] = w;
        zp += w;
    }
    #pragma unroll
    for (int o = 16; o > 0; o >>= 1) zp += __shfl_xor_sync(0xffffffffu, zp, o);
    __syncwarp();

    float2 acc = make_float2(0.f, 0.f);
    int i = 0;
    for (; i + 3 < n; i += 4) {
        float w0 = s_w[wr][i],     w1 = s_w[wr][i + 1];
        float w2 = s_w[wr][i + 2], w3 = s_w[wr][i + 3];
        float2 v0 = __half22float2(hh[(size_t)s_nbr[wr][i]     * 32 + lane]);
        float2 v1 = __half22float2(hh[(size_t)s_nbr[wr][i + 1] * 32 + lane]);
        float2 v2 = __half22float2(hh[(size_t)s_nbr[wr][i + 2] * 32 + lane]);
        float2 v3 = __half22float2(hh[(size_t)s_nbr[wr][i + 3] * 32 + lane]);
        acc.x += w0 * v0.x; acc.y += w0 * v0.y;
        acc.x += w1 * v1.x; acc.y += w1 * v1.y;
        acc.x += w2 * v2.x; acc.y += w2 * v2.y;
        acc.x += w3 * v3.x; acc.y += w3 * v3.y;
    }
    for (; i < n; i++) {
        float w = s_w[wr][i];
        float2 v = __half22float2(hh[(size_t)s_nbr[wr][i] * 32 + lane]);
        acc.x += w * v.x; acc.y += w * v.y;
    }
    float inv = 1.f / zp;
    ((float2*)out)[(size_t)row * 32 + lane] = make_float2(acc.x * inv, acc.y * inv);
}

// ---------------- launcher ----------------
template <typename... Args>
static void launch_pdl(void (*kern)(Args...), dim3 grid, dim3 block,
                       Args... args) {
    cudaLaunchConfig_t cfg = {};
    cfg.gridDim = grid; cfg.blockDim = block; cfg.stream = 0;
    cudaLaunchAttribute at[1];
    at[0].id = cudaLaunchAttributeProgrammaticStreamSerialization;
    at[0].val.programmaticStreamSerializationAllowed = 1;
    cfg.attrs = at; cfg.numAttrs = 1;
    cudaLaunchKernelEx(&cfg, kern, args...);
}

extern "C" void kernel_launch(void* const* d_in, const int* in_sizes, int n_in,
                              void* d_out, int out_size) {
    const float* features = (const float*)d_in[0];   // [4096, 256]
    const float* adj      = (const float*)d_in[1];   // [4096, 4096]
    const float* W_heads  = (const float*)d_in[2];   // [8, 256, 64]
    const float* a_heads  = (const float*)d_in[3];   // [8, 128, 1]
    const float* W_out    = (const float*)d_in[4];   // [512, 64]
    const float* a_out    = (const float*)d_in[5];   // [128, 1]
    float* out = (float*)d_out;                      // [4096, 64]

    int    *cnt, *idxp;
    float  *s1a, *s2a, *x2, *h2p, *s1b, *s2b;
    __half *h1h, *h2h;
    cudaGetSymbolAddress((void**)&cnt,  g_cnt);
    cudaGetSymbolAddress((void**)&idxp, g_idx);
    cudaGetSymbolAddress((void**)&h1h,  g_h1h);
    cudaGetSymbolAddress((void**)&s1a,  g_s1a);
    cudaGetSymbolAddress((void**)&s2a,  g_s2a);
    cudaGetSymbolAddress((void**)&x2,   g_x2);
    cudaGetSymbolAddress((void**)&h2p,  g_h2p);
    cudaGetSymbolAddress((void**)&h2h,  g_h2h);
    cudaGetSymbolAddress((void**)&s1b,  g_s1b);
    cudaGetSymbolAddress((void**)&s2b,  g_s2b);

    // 1. layer1 GEMM (fp16 2-term split MMA) + fused scores + fp16 table
    gemm1_tc<<<dim3(32, 1, 8), 256>>>(features, W_heads, h1h, a_heads, s1a, s2a);

    // 2. layer1 attention with fused CSR build (adj scan overlaps gemm1 via PDL)
    launch_pdl(att1_csr, dim3(NNODES), dim3(256),
               adj, (const __half2*)h1h, (const float*)s1a, (const float*)s2a,
               cnt, idxp, x2);

    // 3. layer2 GEMM (fp16 2-term split, split-K x4 -> 128 blocks)
    launch_pdl(gemm2_tc, dim3(32, SPLITK, 1), dim3(256),
               (const float*)x2, W_out, h2p);

    // 4. reduce partials + layer2 scores + fp16 table
    launch_pdl(reduce_scores2, dim3(NNODES / 8), dim3(256),
               (const float*)h2p, a_out, h2h, s1b, s2b);

    // 5. layer2 attention
    launch_pdl(att2_kernel, dim3(NNODES / 8), dim3(256),
               (const __half2*)h2h, (const float*)s1b, (const float*)s2b,
               (const int*)cnt, (const int*)idxp, out);
}